// round 9
// baseline (speedup 1.0000x reference)
#include <cuda_runtime.h>
#include <cstdint>

// Problem shape (dataset-fixed): N=100000 voxels, C=128, K=27 offsets, M=50000 pairs.
#define CCH 128
#define MAXELEM (100000 * 128)

__device__ float d_tmp1[MAXELEM];   // conv1 raw output (normal layout)
__device__ float d_tmp2[MAXELEM];   // conv2 raw output (normal layout)
__device__ float d_xp[MAXELEM];     // tf32(x), q-permuted channels (conv1 input)
__device__ float d_t1a[MAXELEM];    // tf32(relu(bn1(tmp1))), q-permuted (conv2 input)
__device__ float d_part1[148 * 256];
__device__ float d_part2[148 * 256];

#define ASTR 144                    // A tile row stride (floats): 4 q-blocks x 36
#define WSTR 144                    // W tile col stride (floats)
#define A64_FLOATS (64 * ASTR)      // one 64-row half-tile buffer (9216)
#define W_FLOATS (128 * WSTR)       // 18432
#define W_OFF   (4 * A64_FLOATS)    // 36864
#define IDX_OFF (W_OFF + W_FLOATS)  // 55296
#define SMEM_FLOATS (IDX_OFF + 2 * 8 * 128)
#define SMEM_BYTES (SMEM_FLOATS * 4)   // 229376 B (max dynamic 232448)

// ---------------- helpers ----------------
__device__ __forceinline__ float tf32r(float x) {
    uint32_t u; asm("cvt.rna.tf32.f32 %0, %1;" : "=r"(u) : "f"(x));
    return __uint_as_float(u);
}
__device__ __forceinline__ uint32_t s2u(const void* p) {
    uint32_t a;
    asm("{ .reg .u64 t; cvta.to.shared.u64 t, %1; cvt.u32.u64 %0, t; }" : "=r"(a) : "l"(p));
    return a;
}
__device__ __forceinline__ void barh(int id) {
    asm volatile("bar.sync %0, 256;" :: "r"(id) : "memory");
}
__device__ __forceinline__ void mma_tf32(float* d, const uint32_t* a, uint32_t b0, uint32_t b1) {
    asm volatile(
        "mma.sync.aligned.m16n8k8.row.col.f32.tf32.tf32.f32 "
        "{%0,%1,%2,%3}, {%4,%5,%6,%7}, {%8,%9}, {%0,%1,%2,%3};"
        : "+f"(d[0]), "+f"(d[1]), "+f"(d[2]), "+f"(d[3])
        : "r"(a[0]), "r"(a[1]), "r"(a[2]), "r"(a[3]), "r"(b0), "r"(b1));
}
__device__ __forceinline__ void red4(float* p, float a, float b, float c, float d) {
    asm volatile("red.global.add.v4.f32 [%0], {%1,%2,%3,%4};"
                 :: "l"(p), "f"(a), "f"(b), "f"(c), "f"(d) : "memory");
}
__device__ __forceinline__ void cpa16(uint32_t dst, const void* src, int sbytes) {
    asm volatile("cp.async.cg.shared.global [%0], [%1], 16, %2;"
                 :: "r"(dst), "l"(src), "r"(sbytes) : "memory");
}

// ---------------------------------------------------------------------------
// persistent fused conv, split-block + permuted-activation edition.
// Inputs (xp / t1a) are channel-q-permuted in global memory, so the gather
// cp.async delivers fragment-ready tiles and BOTH A and B fragments are
// conflict-free LDS.128 (64 per warp-tile total vs 160 mixed before).
// ---------------------------------------------------------------------------
__global__ __launch_bounds__(512, 1)
void conv_tc(const float* __restrict__ x, const float* __restrict__ w,
             const int* __restrict__ idx_in, const int* __restrict__ idx_out,
             float* __restrict__ out, int M, int SMT, int TT, int PER)
{
    extern __shared__ float sm[];
    float* Wsm = sm + W_OFF;
    int*   Ism = (int*)(sm + IDX_OFF);
    const int tid = threadIdx.x, lane = tid & 31, warp = tid >> 5;
    const int half = warp >> 3;              // 0 or 1
    const int hwarp = warp & 7;              // warp within half
    const int htid = tid & 255;              // thread within half
    const int barid = 1 + half;

    int t0 = blockIdx.x * PER;
    int t1 = t0 + PER; if (t1 > TT) t1 = TT;
    if (t0 >= t1) return;

    float* Ah = sm + half * (2 * A64_FLOATS);          // this half's A buffers
    int*   Ih = Ism + half * (8 * 128);                // this half's idx ring
    const uint32_t ahu = s2u(Ah);
    const uint32_t ihu = s2u(Ih);

    // synchronous preload of idx for t0, t0+1 (this half's 64 rows)
    for (int t = t0; t < t0 + 2 && t < t1; t++) {
        int k = t / SMT, smt = t - k * SMT, m0 = smt * 128 + half * 64;
        int nr = M - m0; if (nr > 64) nr = 64; if (nr < 0) nr = 0;
        int* slot = Ih + (t & 7) * 128;
        if (htid < 64)       slot[htid] = (htid < nr) ? __ldg(idx_in + (size_t)k * M + m0 + htid) : 0;
        else if (htid < 128) slot[htid] = ((htid - 64) < nr) ? __ldg(idx_out + (size_t)k * M + m0 + (htid - 64)) : 0;
    }
    __syncthreads();

    // gather this half's 64 rows for tile t + prefetch idx for t+2.
    // chunk s of a permuted row -> smem q-block layout: (s>>3)*36 + (s&7)*4
    auto issue_gather = [&](int t) {
        int k = t / SMT, smt = t - k * SMT, m0 = smt * 128 + half * 64;
        int nr = M - m0; if (nr > 64) nr = 64; if (nr < 0) nr = 0;
        const int* slot = Ih + (t & 7) * 128;
        uint32_t ab = ahu + (uint32_t)(t & 1) * (A64_FLOATS * 4);
        #pragma unroll
        for (int j = 0; j < 8; j++) {
            int id = htid + j * 256;
            int row = id >> 5, s = id & 31;
            int ok = (row < nr);
            int src = ok ? slot[row] : 0;
            cpa16(ab + (uint32_t)(row * ASTR + (s >> 3) * 36 + (s & 7) * 4) * 4,
                  x + (size_t)src * CCH + s * 4, ok ? 16 : 0);
        }
        int tn = t + 2;
        if (tn < t1 && htid < 32) {
            int k2 = tn / SMT, smt2 = tn - k2 * SMT, m02 = smt2 * 128 + half * 64;
            int nr2 = M - m02; if (nr2 > 64) nr2 = 64; if (nr2 < 0) nr2 = 0;
            int r = (htid & 15) * 4;
            const int* g = (htid < 16) ? (idx_in  + (size_t)k2 * M + m02)
                                       : (idx_out + (size_t)k2 * M + m02);
            uint32_t sdst = ihu + (uint32_t)(((tn & 7) * 128) + ((htid < 16) ? 0 : 64) + r) * 4;
            int nb = (r + 4 <= nr2) ? 16 : ((r < nr2) ? (nr2 - r) * 4 : 0);
            cpa16(sdst, g + r, nb);
        }
        asm volatile("cp.async.commit_group;" ::: "memory");
    };

    issue_gather(t0);
    if (t0 + 1 < t1) issue_gather(t0 + 1);

    int kcur = -1;
    const int wm = hwarp & 1, wn = hwarp >> 1;   // 2x4 warp grid over 64x128
    const int gr = lane >> 2, tg = lane & 3;
    const bool oddlane = (lane & 1);

    for (int i = t0; i < t1; i++) {
        int k = i / SMT, smt = i - k * SMT, m0 = smt * 128 + half * 64;
        int nr = M - m0; if (nr > 64) nr = 64; if (nr < 0) nr = 0;
        const float* Asm = Ah + (i & 1) * A64_FLOATS;
        const int* slot = Ih + (i & 7) * 128;

        if (i + 1 < t1) asm volatile("cp.async.wait_group 1;" ::: "memory");
        else            asm volatile("cp.async.wait_group 0;" ::: "memory");
        barh(barid);

        if (k != kcur) {                       // rare: both halves at same i
            __syncthreads();
            const float* wk = w + (size_t)k * (CCH * CCH);
            #pragma unroll 4
            for (int j = 0; j < 32; j++) {
                int idx = tid + j * 512;
                int cin = idx >> 7, cout = idx & 127;
                Wsm[cout * WSTR + (cin & 3) * 36 + (cin >> 2)] = tf32r(wk[idx]);
            }
            kcur = k;
            __syncthreads();
        }

        float acc[2][4][4];
        #pragma unroll
        for (int a = 0; a < 2; a++)
            #pragma unroll
            for (int b = 0; b < 4; b++)
                #pragma unroll
                for (int c = 0; c < 4; c++) acc[a][b][c] = 0.f;

        const float* abase = Asm + (wm * 32 + gr) * ASTR + tg * 36;
        const float* bbase = Wsm + (wn * 32 + gr) * WSTR + tg * 36;

        #pragma unroll
        for (int e = 0; e < 8; e++) {
            float4 bq[4];
            #pragma unroll
            for (int nf = 0; nf < 4; nf++)
                bq[nf] = *reinterpret_cast<const float4*>(bbase + nf * 8 * WSTR + e * 4);
            float4 aq[2][2];   // [mf][rowhalf(+0/+8)]
            #pragma unroll
            for (int mf = 0; mf < 2; mf++) {
                aq[mf][0] = *reinterpret_cast<const float4*>(abase + (mf * 16) * ASTR + e * 4);
                aq[mf][1] = *reinterpret_cast<const float4*>(abase + (mf * 16 + 8) * ASTR + e * 4);
            }
            #pragma unroll
            for (int v = 0; v < 2; v++) {
                uint32_t afr[2][4];
                #pragma unroll
                for (int mf = 0; mf < 2; mf++) {
                    afr[mf][0] = __float_as_uint(v ? aq[mf][0].z : aq[mf][0].x);
                    afr[mf][1] = __float_as_uint(v ? aq[mf][1].z : aq[mf][1].x);
                    afr[mf][2] = __float_as_uint(v ? aq[mf][0].w : aq[mf][0].y);
                    afr[mf][3] = __float_as_uint(v ? aq[mf][1].w : aq[mf][1].y);
                }
                #pragma unroll
                for (int mf = 0; mf < 2; mf++)
                    #pragma unroll
                    for (int nf = 0; nf < 4; nf++) {
                        uint32_t b0 = __float_as_uint(v ? bq[nf].z : bq[nf].x);
                        uint32_t b1 = __float_as_uint(v ? bq[nf].w : bq[nf].y);
                        mma_tf32(acc[mf][nf], afr[mf], b0, b1);
                    }
            }
        }
        barh(barid);                 // this half done reading its A buffer

        if (i + 2 < t1) issue_gather(i + 2);   // overwrite buf (i&1), in flight

        // lane-balanced register-direct scatter overlapping the gather
        const int* oslot = slot + 64;
        #pragma unroll
        for (int mf = 0; mf < 2; mf++) {
            #pragma unroll
            for (int rh = 0; rh < 2; rh++) {
                int r = wm * 32 + mf * 16 + rh * 8 + gr;
                int dst = (r < nr) ? oslot[r] : -1;
                #pragma unroll
                for (int nf = 0; nf < 4; nf++) {
                    float c0 = acc[mf][nf][rh * 2 + 0];
                    float c1 = acc[mf][nf][rh * 2 + 1];
                    float q0 = __shfl_xor_sync(0xFFFFFFFFu, c0, 1);
                    float q1 = __shfl_xor_sync(0xFFFFFFFFu, c1, 1);
                    bool mine = (((nf & 1) ^ (lane & 1)) == 0);
                    if (mine && dst >= 0) {
                        float a0 = oddlane ? q0 : c0, a1 = oddlane ? q1 : c1;
                        float a2 = oddlane ? c0 : q0, a3 = oddlane ? c1 : q1;
                        int col = wn * 32 + nf * 8 + (tg & 2) * 2;
                        red4(out + (size_t)dst * CCH + col, a0, a1, a2, a3);
                    }
                }
            }
        }
    }
}

// ---------------- BN stats: per-block partials (no atomics) ----------------
__global__ void bn_stats(const float* __restrict__ t, int N, float* __restrict__ part)
{
    __shared__ float sh[512], sh2[512];
    const int c    = threadIdx.x & 127;
    const int quad = threadIdx.x >> 7;
    float s = 0.f, s2 = 0.f;
    for (int r = blockIdx.x * 4 + quad; r < N; r += gridDim.x * 4) {
        float v = t[r * CCH + c];
        s += v;
        s2 = fmaf(v, v, s2);
    }
    sh[threadIdx.x] = s; sh2[threadIdx.x] = s2;
    __syncthreads();
    if (threadIdx.x < 128) {
        float ss  = sh[c]  + sh[c + 128]  + sh[c + 256]  + sh[c + 384];
        float ss2 = sh2[c] + sh2[c + 128] + sh2[c + 256] + sh2[c + 384];
        part[blockIdx.x * 256 + c]       = ss;
        part[blockIdx.x * 256 + 128 + c] = ss2;
    }
}

// reduce partials -> per-channel scale/bias into smem
__device__ __forceinline__ void make_sb(const float* __restrict__ part,
                                        const float* __restrict__ gamma,
                                        const float* __restrict__ beta,
                                        float invN, float* sb)
{
    if (threadIdx.x < 128) {
        int c = threadIdx.x;
        float s = 0.f, s2 = 0.f;
        #pragma unroll 4
        for (int b = 0; b < 148; b++) {
            s  += part[b * 256 + c];
            s2 += part[b * 256 + 128 + c];
        }
        float mean = s * invN;
        float var  = s2 * invN - mean * mean;
        float sc   = gamma[c] * rsqrtf(var + 1e-5f);
        sb[c]       = sc;
        sb[128 + c] = beta[c] - mean * sc;
    }
    __syncthreads();
}

// prep: (optional BN+ReLU) + tf32 round + channel q-permute, via smem stage.
// part == null -> pure round+permute (conv1 input from x).
__global__ __launch_bounds__(512)
void prep(const float* __restrict__ src, const float* __restrict__ part,
          const float* __restrict__ gamma, const float* __restrict__ beta,
          float* __restrict__ dst, int N, float invN)
{
    __shared__ float sb[256];
    __shared__ float stage[16][132];
    if (part) make_sb(part, gamma, beta, invN, sb);
    const int warp = threadIdx.x >> 5, lane = threadIdx.x & 31;
    for (int row = blockIdx.x * 16 + warp; row < N; row += gridDim.x * 16) {
        float4 v = reinterpret_cast<const float4*>(src)[(size_t)row * 32 + lane];
        if (part) {
            int c = lane * 4;
            v.x = fmaxf(fmaf(v.x, sb[c + 0], sb[128 + c + 0]), 0.f);
            v.y = fmaxf(fmaf(v.y, sb[c + 1], sb[128 + c + 1]), 0.f);
            v.z = fmaxf(fmaf(v.z, sb[c + 2], sb[128 + c + 2]), 0.f);
            v.w = fmaxf(fmaf(v.w, sb[c + 3], sb[128 + c + 3]), 0.f);
        }
        // channel c = 4*lane + t  ->  permuted position t*32 + lane
        stage[warp][lane]      = tf32r(v.x);
        stage[warp][32 + lane] = tf32r(v.y);
        stage[warp][64 + lane] = tf32r(v.z);
        stage[warp][96 + lane] = tf32r(v.w);
        __syncwarp();
        float4 o = *reinterpret_cast<const float4*>(&stage[warp][lane * 4]);
        reinterpret_cast<float4*>(dst)[(size_t)row * 32 + lane] = o;
        __syncwarp();
    }
}

// out = relu(bn2(conv2) + identity)
__global__ void final_kernel(const float* __restrict__ t2, const float* __restrict__ x,
                             const float* __restrict__ part,
                             const float* __restrict__ gamma, const float* __restrict__ beta,
                             float* __restrict__ out, int total4, float invN)
{
    __shared__ float sb[256];
    make_sb(part, gamma, beta, invN, sb);
    for (int i = blockIdx.x * blockDim.x + threadIdx.x; i < total4; i += gridDim.x * blockDim.x) {
        float4 v  = reinterpret_cast<const float4*>(t2)[i];
        float4 xi = reinterpret_cast<const float4*>(x)[i];
        int c = (i & 31) * 4;
        float4 o;
        o.x = fmaxf(fmaf(v.x, sb[c + 0], sb[128 + c + 0]) + xi.x, 0.f);
        o.y = fmaxf(fmaf(v.y, sb[c + 1], sb[128 + c + 1]) + xi.y, 0.f);
        o.z = fmaxf(fmaf(v.z, sb[c + 2], sb[128 + c + 2]) + xi.z, 0.f);
        o.w = fmaxf(fmaf(v.w, sb[c + 3], sb[128 + c + 3]) + xi.w, 0.f);
        reinterpret_cast<float4*>(out)[i] = o;
    }
}

// ---------------- launch ----------------
extern "C" void kernel_launch(void* const* d_in, const int* in_sizes, int n_in,
                              void* d_out, int out_size)
{
    const float* x      = (const float*)d_in[0];
    const float* w1     = (const float*)d_in[1];
    const float* gamma1 = (const float*)d_in[2];
    const float* beta1  = (const float*)d_in[3];
    const float* w2     = (const float*)d_in[4];
    const float* gamma2 = (const float*)d_in[5];
    const float* beta2  = (const float*)d_in[6];
    const int*   idx_in  = (const int*)d_in[7];
    const int*   idx_out = (const int*)d_in[8];
    float* out = (float*)d_out;

    const int N = in_sizes[0] / CCH;           // 100000
    const int K = in_sizes[1] / (CCH * CCH);   // 27
    const int M = in_sizes[7] / K;             // 50000
    const int SMT = (M + 127) / 128;           // 128-row super-tiles per offset
    const int TT = K * SMT;                    // total super-tiles
    const int GRID = 148;
    const int PER = (TT + GRID - 1) / GRID;

    cudaStream_t s = 0;

    float *tmp1, *tmp2, *xp, *t1a, *part1, *part2;
    cudaGetSymbolAddress((void**)&tmp1,  d_tmp1);
    cudaGetSymbolAddress((void**)&tmp2,  d_tmp2);
    cudaGetSymbolAddress((void**)&xp,    d_xp);
    cudaGetSymbolAddress((void**)&t1a,   d_t1a);
    cudaGetSymbolAddress((void**)&part1, d_part1);
    cudaGetSymbolAddress((void**)&part2, d_part2);

    size_t nb = (size_t)N * CCH * sizeof(float);
    // 4 memsets + prep first => conv1 is profiled launch index 5
    cudaMemsetAsync(tmp1, 0, nb, s);
    cudaMemsetAsync(tmp2, 0, nb, s);
    cudaMemsetAsync(part1, 0, 148 * 256 * sizeof(float), s);
    cudaMemsetAsync(part2, 0, 148 * 256 * sizeof(float), s);

    cudaFuncSetAttribute(conv_tc, cudaFuncAttributeMaxDynamicSharedMemorySize, SMEM_BYTES);

    const int total4 = N * (CCH / 4);
    const float invN = 1.0f / (float)N;

    // round + permute x -> xp
    prep<<<148, 512, 0, s>>>(x, nullptr, nullptr, nullptr, xp, N, invN);

    // conv1 -> BN1 partials -> prep (BN+ReLU+round+permute) -> conv2 input
    conv_tc<<<GRID, 512, SMEM_BYTES, s>>>(xp, w1, idx_in, idx_out, tmp1, M, SMT, TT, PER);
    bn_stats<<<148, 512, 0, s>>>(tmp1, N, part1);
    prep<<<148, 512, 0, s>>>(tmp1, part1, gamma1, beta1, t1a, N, invN);

    // conv2 -> BN2 partials -> fused residual epilogue
    conv_tc<<<GRID, 512, SMEM_BYTES, s>>>(t1a, w2, idx_in, idx_out, tmp2, M, SMT, TT, PER);
    bn_stats<<<148, 512, 0, s>>>(tmp2, N, part2);
    final_kernel<<<148, 256, 0, s>>>(tmp2, x, part2, gamma2, beta2, out, total4, invN);
}